// round 8
// baseline (speedup 1.0000x reference)
#include <cuda_runtime.h>
#include <cuda_bf16.h>

// Problem constants
#define BB 16
#define TT 24
#define NN 2048
#define FF 64
#define BT (BB*TT)          // 384
#define NF (NN*FF)          // 131072
#define NF4 (NF/4)          // 32768 float4 per (b,t) row
#define KSPLIT 16
#define NGROUP 4            // batches per group
#define GROUPS (BB/NGROUP)  // 4
#define GBT (NGROUP*TT)     // 96 bt rows per group

// Scratch (device globals; no allocation allowed). All fully overwritten each call.
__device__ float d_rhs[BT*NN];         // 3 MB
__device__ float d_lfp[4*BT*FF];       // lhs_f partials (4 quarters per bt)
__device__ float d_Gp [KSPLIT*BT*FF];  // K-split partials of G
__device__ float d_A  [BB*TT*TT];      // attention weights

// ---------------------------------------------------------------------------
// Kernel 1 (per group): pass over x. Each CTA (128 thr) handles one QUARTER
// of the n-range of one (b,t). grid = GBT*4 = 384 CTAs per group.
//   rhs[n]   = sum_f x[n,f]*U3[f]
//   lfp[bt*4+quarter][f] partial of sum_n x[n,f]*U1[n]
// ---------------------------------------------------------------------------
__global__ __launch_bounds__(128) void k1_pass(
    const float* __restrict__ x, const float* __restrict__ U1,
    const float* __restrict__ U3, float* __restrict__ rhs,
    float* __restrict__ lfp, int bt0)
{
    const int btl  = blockIdx.x >> 2;
    const int quar = blockIdx.x & 3;
    const int bt   = bt0 + btl;
    const int w    = threadIdx.x >> 5;
    const int lane = threadIdx.x & 31;
    const int r    = lane >> 2;
    const int q    = lane & 3;
    const float4* xb = (const float4*)(x + (size_t)bt * NF);

    float4 u3[4];
    #pragma unroll
    for (int j = 0; j < 4; j++) u3[j] = ((const float4*)U3)[q + 4*j];

    float4 acc[4];
    #pragma unroll
    for (int j = 0; j < 4; j++) acc[j] = make_float4(0.f,0.f,0.f,0.f);

    const int n0 = quar * 512 + w * 128;
    #pragma unroll 4
    for (int k = 0; k < 16; k++) {
        const int n = n0 + 8*k + r;
        const float4* row = xb + (size_t)n * 16;
        const float u1 = __ldg(U1 + n);
        float d = 0.f;
        #pragma unroll
        for (int j = 0; j < 4; j++) {
            float4 v = row[q + 4*j];
            d += v.x*u3[j].x + v.y*u3[j].y + v.z*u3[j].z + v.w*u3[j].w;
            acc[j].x += v.x*u1; acc[j].y += v.y*u1;
            acc[j].z += v.z*u1; acc[j].w += v.w*u1;
        }
        d += __shfl_down_sync(0xffffffffu, d, 2, 4);
        d += __shfl_down_sync(0xffffffffu, d, 1, 4);
        if (q == 0) rhs[bt*NN + n] = d;
    }

    #pragma unroll
    for (int off = 16; off >= 4; off >>= 1) {
        #pragma unroll
        for (int j = 0; j < 4; j++) {
            acc[j].x += __shfl_down_sync(0xffffffffu, acc[j].x, off);
            acc[j].y += __shfl_down_sync(0xffffffffu, acc[j].y, off);
            acc[j].z += __shfl_down_sync(0xffffffffu, acc[j].z, off);
            acc[j].w += __shfl_down_sync(0xffffffffu, acc[j].w, off);
        }
    }

    __shared__ float sred[4][FF];
    if (lane < 4) {
        #pragma unroll
        for (int j = 0; j < 4; j++)
            ((float4*)sred[w])[q + 4*j] = acc[j];
    }
    __syncthreads();
    if (threadIdx.x < FF) {
        float t = 0.f;
        #pragma unroll
        for (int p = 0; p < 4; p++) t += sred[p][threadIdx.x];
        lfp[(bt*4 + quar)*FF + threadIdx.x] = t;
    }
}

// ---------------------------------------------------------------------------
// Kernel 2 (per group): G = rhs(96 x 2048) @ U2(2048 x 64), K-split 16.
// Thread = 4 rows x 4 cols. grid = (3, 16) per group.
// ---------------------------------------------------------------------------
__global__ __launch_bounds__(128) void k2_gemm(
    const float* __restrict__ rhs, const float* __restrict__ U2,
    float* __restrict__ Gp, int bt0)
{
    __shared__ float4 Us4[64*16];
    __shared__ float  Rs [32*68];
    const int m0 = bt0 + blockIdx.x * 32;
    const int k0 = blockIdx.y * 128;
    const int c4 = threadIdx.x & 15;
    const int rg = threadIdx.x >> 4;

    float4 acc[4];
    #pragma unroll
    for (int r = 0; r < 4; r++) acc[r] = make_float4(0.f,0.f,0.f,0.f);

    for (int kc = 0; kc < 128; kc += 64) {
        const int kb = k0 + kc;
        __syncthreads();
        #pragma unroll
        for (int i = 0; i < 8; i++) {
            int e = threadIdx.x + i*128;
            int kk = e >> 4, cc = e & 15;
            Us4[e] = ((const float4*)(U2 + (size_t)(kb + kk)*FF))[cc];
        }
        #pragma unroll
        for (int i = 0; i < 4; i++) {
            int e = threadIdx.x + i*128;
            int row = e >> 4, kq = e & 15;
            float4 v = *(const float4*)(rhs + (size_t)(m0 + row)*NN + kb + kq*4);
            *(float4*)&Rs[row*68 + kq*4] = v;
        }
        __syncthreads();
        #pragma unroll
        for (int kk = 0; kk < 64; kk++) {
            const float4 u = Us4[kk*16 + c4];
            #pragma unroll
            for (int r = 0; r < 4; r++) {
                const float rv = Rs[(rg*4 + r)*68 + kk];
                acc[r].x += rv*u.x; acc[r].y += rv*u.y;
                acc[r].z += rv*u.z; acc[r].w += rv*u.w;
            }
        }
    }
    float* g = Gp + (size_t)blockIdx.y * (BT*FF);
    #pragma unroll
    for (int r = 0; r < 4; r++)
        *(float4*)&g[(m0 + rg*4 + r)*FF + c4*4] = acc[r];
}

// ---------------------------------------------------------------------------
// Kernel 3 (per group): per batch: product -> sigmoid(+be) -> E -> softmax.
// ---------------------------------------------------------------------------
__global__ __launch_bounds__(576) void k3_scores(
    const float* __restrict__ lfp, const float* __restrict__ Gp,
    const float* __restrict__ be, const float* __restrict__ Ve,
    float* __restrict__ A, int b0)
{
    const int b = b0 + blockIdx.x;
    __shared__ float lfs[TT*65], Gs[TT*65], sg[TT*25], Em[TT*25];
    __shared__ float cmax[TT], csum[TT];
    const int tid = threadIdx.x;

    for (int e = tid; e < TT*FF; e += 576) {
        int t = e >> 6, f = e & 63;
        const int bt = b*TT + t;
        float lv = 0.f;
        #pragma unroll
        for (int p = 0; p < 4; p++) lv += lfp[(bt*4 + p)*FF + f];
        lfs[t*65 + f] = lv;
        float g = 0.f;
        #pragma unroll
        for (int ks = 0; ks < KSPLIT; ks++)
            g += Gp[(size_t)ks*(BT*FF) + bt*FF + f];
        Gs[t*65 + f] = g;
    }
    __syncthreads();

    const int t = tid / TT;
    const int s = tid % TT;
    float p = 0.f;
    #pragma unroll
    for (int f = 0; f < FF; f++)
        p += lfs[t*65 + f] * Gs[s*65 + f];
    sg[t*25 + s] = 1.f / (1.f + __expf(-(p + be[t*TT + s])));
    __syncthreads();

    float e = 0.f;
    #pragma unroll
    for (int s2 = 0; s2 < TT; s2++)
        e += Ve[t*TT + s2] * sg[s2*25 + s];
    Em[t*25 + s] = e;
    __syncthreads();

    if (t == 0) {
        float m = -1e30f;
        #pragma unroll
        for (int tt2 = 0; tt2 < TT; tt2++) m = fmaxf(m, Em[tt2*25 + s]);
        cmax[s] = m;
    }
    __syncthreads();
    const float ex = __expf(Em[t*25 + s] - cmax[s]);
    Em[t*25 + s] = ex;
    __syncthreads();
    if (t == 0) {
        float sm = 0.f;
        #pragma unroll
        for (int tt2 = 0; tt2 < TT; tt2++) sm += Em[tt2*25 + s];
        csum[s] = sm;
    }
    __syncthreads();
    A[b*TT*TT + t*TT + s] = ex / csum[s];
}

// ---------------------------------------------------------------------------
// Kernel 4 (per group): out[b,s,nf] = sum_t x[b,t,nf] * A[b,t,s].
// float4 column per thread, s in pairs, 4 CTAs/SM. Runs while x[group] is
// still L2-resident from its k1 (pipelined schedule).
// ---------------------------------------------------------------------------
__global__ __launch_bounds__(128, 4) void k4_out(
    const float4* __restrict__ x4, const float* __restrict__ A,
    float4* __restrict__ out4, int b0)
{
    __shared__ float2 As2[TT*12];
    const int b = b0 + blockIdx.y;
    const float2* Ab2 = (const float2*)(A + b*TT*TT);
    for (int i = threadIdx.x; i < TT*12; i += 128)
        As2[i] = Ab2[i];
    __syncthreads();

    const size_t c = (size_t)blockIdx.x * 128 + threadIdx.x;
    const float4* xb = x4 + (size_t)b * TT * NF4 + c;

    float4 xr[TT];
    #pragma unroll
    for (int t = 0; t < TT; t++) xr[t] = xb[(size_t)t * NF4];

    float4* ob = out4 + (size_t)b * TT * NF4 + c;
    #pragma unroll 1
    for (int sp = 0; sp < 12; sp++) {
        float4 a0 = make_float4(0.f,0.f,0.f,0.f);
        float4 a1 = make_float4(0.f,0.f,0.f,0.f);
        #pragma unroll
        for (int t = 0; t < TT; t++) {
            const float2 av = As2[t*12 + sp];
            a0.x += xr[t].x*av.x; a0.y += xr[t].y*av.x; a0.z += xr[t].z*av.x; a0.w += xr[t].w*av.x;
            a1.x += xr[t].x*av.y; a1.y += xr[t].y*av.y; a1.z += xr[t].z*av.y; a1.w += xr[t].w*av.y;
        }
        ob[(size_t)(2*sp    ) * NF4] = a0;
        ob[(size_t)(2*sp + 1) * NF4] = a1;
    }
}

// ---------------------------------------------------------------------------
// Pipelined launch: main stream runs the big x-pass kernels; side stream runs
// the tiny score chain, forked/joined with events (capture-legal pattern).
// Streams/events created once on the (non-captured) correctness call.
// ---------------------------------------------------------------------------
extern "C" void kernel_launch(void* const* d_in, const int* in_sizes, int n_in,
                              void* d_out, int out_size)
{
    const float* x  = (const float*)d_in[0];
    const float* U1 = (const float*)d_in[1];
    const float* U2 = (const float*)d_in[2];
    const float* U3 = (const float*)d_in[3];
    const float* be = (const float*)d_in[4];
    const float* Ve = (const float*)d_in[5];

    float *rhs, *lfp, *Gp, *A;
    cudaGetSymbolAddress((void**)&rhs, d_rhs);
    cudaGetSymbolAddress((void**)&lfp, d_lfp);
    cudaGetSymbolAddress((void**)&Gp,  d_Gp);
    cudaGetSymbolAddress((void**)&A,   d_A);

    static cudaStream_t sB = nullptr;
    static cudaEvent_t  eK1[GROUPS], eS[GROUPS];
    if (!sB) {
        cudaStreamCreateWithFlags(&sB, cudaStreamNonBlocking);
        for (int g = 0; g < GROUPS; g++) {
            cudaEventCreateWithFlags(&eK1[g], cudaEventDisableTiming);
            cudaEventCreateWithFlags(&eS[g],  cudaEventDisableTiming);
        }
    }

    // helper lambdas for per-group launches
    auto launch_k1 = [&](int g) {
        k1_pass<<<GBT*4, 128>>>(x, U1, U3, rhs, lfp, g*GBT);
        cudaEventRecord(eK1[g], 0);
    };
    auto launch_scores = [&](int g) {
        cudaStreamWaitEvent(sB, eK1[g], 0);
        k2_gemm<<<dim3(GBT/32, KSPLIT), 128, 0, sB>>>(rhs, U2, Gp, g*GBT);
        k3_scores<<<NGROUP, 576, 0, sB>>>(lfp, Gp, be, Ve, A, g*NGROUP);
        cudaEventRecord(eS[g], sB);
    };
    auto launch_k4 = [&](int g) {
        cudaStreamWaitEvent(0, eS[g], 0);
        k4_out<<<dim3(NF4/128, NGROUP), 128>>>((const float4*)x, A,
                                               (float4*)d_out, g*NGROUP);
    };

    // Pipeline: k1g0 k1g1 k4g0 k1g2 k4g1 k1g3 k4g2 k4g3; scores on side stream.
    launch_k1(0);
    launch_scores(0);
    launch_k1(1);
    launch_scores(1);
    launch_k4(0);
    launch_k1(2);
    launch_scores(2);
    launch_k4(1);
    launch_k1(3);
    launch_scores(3);
    launch_k4(2);
    launch_k4(3);
}

// round 9
// speedup vs baseline: 1.2341x; 1.2341x over previous
#include <cuda_runtime.h>
#include <cuda_bf16.h>

// Problem constants
#define BB 16
#define TT 24
#define NN 2048
#define FF 64
#define BT (BB*TT)          // 384
#define NF (NN*FF)          // 131072
#define NF4 (NF/4)          // 32768 float4 per (b,t) row
#define KSPLIT 16
#define HB (BB/2)           // 8 batches per half
#define HBT (HB*TT)         // 192 bt rows per half

// Scratch (device globals; no allocation allowed). All fully overwritten each call.
__device__ float d_rhs[BT*NN];         // 3 MB
__device__ float d_lfp[8*BT*FF];       // lhs_f partials (8 octants per bt)
__device__ float d_Gp [KSPLIT*BT*FF];  // K-split partials of G
__device__ float d_A  [BB*TT*TT];      // attention weights

// ---------------------------------------------------------------------------
// Kernel 1 (per half): pass over x. Each CTA (128 thr) handles one OCTANT
// (256 rows) of the n-range of one (b,t). grid = HBT*8 = 1536 CTAs per half
// -> 10.4 CTAs/SM, high occupancy for DRAM latency hiding.
//   rhs[n]        = sum_f x[n,f]*U3[f]
//   lfp[bt*8+oct] = partial over this octant of sum_n x[n,f]*U1[n]
// ---------------------------------------------------------------------------
__global__ __launch_bounds__(128) void k1_pass(
    const float* __restrict__ x, const float* __restrict__ U1,
    const float* __restrict__ U3, float* __restrict__ rhs,
    float* __restrict__ lfp, int bt0)
{
    const int btl  = blockIdx.x >> 3;
    const int oct  = blockIdx.x & 7;
    const int bt   = bt0 + btl;
    const int w    = threadIdx.x >> 5;
    const int lane = threadIdx.x & 31;
    const int r    = lane >> 2;
    const int q    = lane & 3;
    const float4* xb = (const float4*)(x + (size_t)bt * NF);

    float4 u3[4];
    #pragma unroll
    for (int j = 0; j < 4; j++) u3[j] = ((const float4*)U3)[q + 4*j];

    float4 acc[4];
    #pragma unroll
    for (int j = 0; j < 4; j++) acc[j] = make_float4(0.f,0.f,0.f,0.f);

    const int n0 = oct * 256 + w * 64;
    #pragma unroll 4
    for (int k = 0; k < 8; k++) {
        const int n = n0 + 8*k + r;
        const float4* row = xb + (size_t)n * 16;
        const float u1 = __ldg(U1 + n);
        float d = 0.f;
        #pragma unroll
        for (int j = 0; j < 4; j++) {
            float4 v = row[q + 4*j];
            d += v.x*u3[j].x + v.y*u3[j].y + v.z*u3[j].z + v.w*u3[j].w;
            acc[j].x += v.x*u1; acc[j].y += v.y*u1;
            acc[j].z += v.z*u1; acc[j].w += v.w*u1;
        }
        d += __shfl_down_sync(0xffffffffu, d, 2, 4);
        d += __shfl_down_sync(0xffffffffu, d, 1, 4);
        if (q == 0) rhs[bt*NN + n] = d;
    }

    #pragma unroll
    for (int off = 16; off >= 4; off >>= 1) {
        #pragma unroll
        for (int j = 0; j < 4; j++) {
            acc[j].x += __shfl_down_sync(0xffffffffu, acc[j].x, off);
            acc[j].y += __shfl_down_sync(0xffffffffu, acc[j].y, off);
            acc[j].z += __shfl_down_sync(0xffffffffu, acc[j].z, off);
            acc[j].w += __shfl_down_sync(0xffffffffu, acc[j].w, off);
        }
    }

    __shared__ float sred[4][FF];
    if (lane < 4) {
        #pragma unroll
        for (int j = 0; j < 4; j++)
            ((float4*)sred[w])[q + 4*j] = acc[j];
    }
    __syncthreads();
    if (threadIdx.x < FF) {
        float t = 0.f;
        #pragma unroll
        for (int p = 0; p < 4; p++) t += sred[p][threadIdx.x];
        lfp[(bt*8 + oct)*FF + threadIdx.x] = t;
    }
}

// ---------------------------------------------------------------------------
// Kernel 2 (per half): G = rhs(192 x 2048) @ U2(2048 x 64), K-split 16.
// Thread = 4 rows x 4 cols. grid = (6, 16) per half.
// ---------------------------------------------------------------------------
__global__ __launch_bounds__(128) void k2_gemm(
    const float* __restrict__ rhs, const float* __restrict__ U2,
    float* __restrict__ Gp, int bt0)
{
    __shared__ float4 Us4[64*16];
    __shared__ float  Rs [32*68];
    const int m0 = bt0 + blockIdx.x * 32;
    const int k0 = blockIdx.y * 128;
    const int c4 = threadIdx.x & 15;
    const int rg = threadIdx.x >> 4;

    float4 acc[4];
    #pragma unroll
    for (int r = 0; r < 4; r++) acc[r] = make_float4(0.f,0.f,0.f,0.f);

    for (int kc = 0; kc < 128; kc += 64) {
        const int kb = k0 + kc;
        __syncthreads();
        #pragma unroll
        for (int i = 0; i < 8; i++) {
            int e = threadIdx.x + i*128;
            int kk = e >> 4, cc = e & 15;
            Us4[e] = ((const float4*)(U2 + (size_t)(kb + kk)*FF))[cc];
        }
        #pragma unroll
        for (int i = 0; i < 4; i++) {
            int e = threadIdx.x + i*128;
            int row = e >> 4, kq = e & 15;
            float4 v = *(const float4*)(rhs + (size_t)(m0 + row)*NN + kb + kq*4);
            *(float4*)&Rs[row*68 + kq*4] = v;
        }
        __syncthreads();
        #pragma unroll
        for (int kk = 0; kk < 64; kk++) {
            const float4 u = Us4[kk*16 + c4];
            #pragma unroll
            for (int r = 0; r < 4; r++) {
                const float rv = Rs[(rg*4 + r)*68 + kk];
                acc[r].x += rv*u.x; acc[r].y += rv*u.y;
                acc[r].z += rv*u.z; acc[r].w += rv*u.w;
            }
        }
    }
    float* g = Gp + (size_t)blockIdx.y * (BT*FF);
    #pragma unroll
    for (int r = 0; r < 4; r++)
        *(float4*)&g[(m0 + rg*4 + r)*FF + c4*4] = acc[r];
}

// ---------------------------------------------------------------------------
// Kernel 3 (per half): per batch: product -> sigmoid(+be) -> E -> softmax.
// ---------------------------------------------------------------------------
__global__ __launch_bounds__(576) void k3_scores(
    const float* __restrict__ lfp, const float* __restrict__ Gp,
    const float* __restrict__ be, const float* __restrict__ Ve,
    float* __restrict__ A, int b0)
{
    const int b = b0 + blockIdx.x;
    __shared__ float lfs[TT*65], Gs[TT*65], sg[TT*25], Em[TT*25];
    __shared__ float cmax[TT], csum[TT];
    const int tid = threadIdx.x;

    for (int e = tid; e < TT*FF; e += 576) {
        int t = e >> 6, f = e & 63;
        const int bt = b*TT + t;
        float lv = 0.f;
        #pragma unroll
        for (int p = 0; p < 8; p++) lv += lfp[(bt*8 + p)*FF + f];
        lfs[t*65 + f] = lv;
        float g = 0.f;
        #pragma unroll
        for (int ks = 0; ks < KSPLIT; ks++)
            g += Gp[(size_t)ks*(BT*FF) + bt*FF + f];
        Gs[t*65 + f] = g;
    }
    __syncthreads();

    const int t = tid / TT;
    const int s = tid % TT;
    float p = 0.f;
    #pragma unroll
    for (int f = 0; f < FF; f++)
        p += lfs[t*65 + f] * Gs[s*65 + f];
    sg[t*25 + s] = 1.f / (1.f + __expf(-(p + be[t*TT + s])));
    __syncthreads();

    float e = 0.f;
    #pragma unroll
    for (int s2 = 0; s2 < TT; s2++)
        e += Ve[t*TT + s2] * sg[s2*25 + s];
    Em[t*25 + s] = e;
    __syncthreads();

    if (t == 0) {
        float m = -1e30f;
        #pragma unroll
        for (int tt2 = 0; tt2 < TT; tt2++) m = fmaxf(m, Em[tt2*25 + s]);
        cmax[s] = m;
    }
    __syncthreads();
    const float ex = __expf(Em[t*25 + s] - cmax[s]);
    Em[t*25 + s] = ex;
    __syncthreads();
    if (t == 0) {
        float sm = 0.f;
        #pragma unroll
        for (int tt2 = 0; tt2 < TT; tt2++) sm += Em[tt2*25 + s];
        csum[s] = sm;
    }
    __syncthreads();
    A[b*TT*TT + t*TT + s] = ex / csum[s];
}

// ---------------------------------------------------------------------------
// Kernel 4 (per half): out[b,s,nf] = sum_t x[b,t,nf] * A[b,t,s].
// float4 column per thread, s in pairs, 4 CTAs/SM. Reverse-b within the half
// so the first waves hit x rows still L2-resident from the preceding k1.
// ---------------------------------------------------------------------------
__global__ __launch_bounds__(128, 4) void k4_out(
    const float4* __restrict__ x4, const float* __restrict__ A,
    float4* __restrict__ out4, int b0)
{
    __shared__ float2 As2[TT*12];
    const int b = b0 + (HB - 1) - blockIdx.y;
    const float2* Ab2 = (const float2*)(A + b*TT*TT);
    for (int i = threadIdx.x; i < TT*12; i += 128)
        As2[i] = Ab2[i];
    __syncthreads();

    const size_t c = (size_t)blockIdx.x * 128 + threadIdx.x;
    const float4* xb = x4 + (size_t)b * TT * NF4 + c;

    float4 xr[TT];
    #pragma unroll
    for (int t = 0; t < TT; t++) xr[t] = xb[(size_t)t * NF4];

    float4* ob = out4 + (size_t)b * TT * NF4 + c;
    #pragma unroll 1
    for (int sp = 0; sp < 12; sp++) {
        float4 a0 = make_float4(0.f,0.f,0.f,0.f);
        float4 a1 = make_float4(0.f,0.f,0.f,0.f);
        #pragma unroll
        for (int t = 0; t < TT; t++) {
            const float2 av = As2[t*12 + sp];
            a0.x += xr[t].x*av.x; a0.y += xr[t].y*av.x; a0.z += xr[t].z*av.x; a0.w += xr[t].w*av.x;
            a1.x += xr[t].x*av.y; a1.y += xr[t].y*av.y; a1.z += xr[t].z*av.y; a1.w += xr[t].w*av.y;
        }
        ob[(size_t)(2*sp    ) * NF4] = a0;
        ob[(size_t)(2*sp + 1) * NF4] = a1;
    }
}

// ---------------------------------------------------------------------------
// Two-half pipeline: main stream runs k1a, k1b, k4b (hot), k4a; side stream
// runs the tiny score chains, hidden under k1b / k4b.
// ---------------------------------------------------------------------------
extern "C" void kernel_launch(void* const* d_in, const int* in_sizes, int n_in,
                              void* d_out, int out_size)
{
    const float* x  = (const float*)d_in[0];
    const float* U1 = (const float*)d_in[1];
    const float* U2 = (const float*)d_in[2];
    const float* U3 = (const float*)d_in[3];
    const float* be = (const float*)d_in[4];
    const float* Ve = (const float*)d_in[5];

    float *rhs, *lfp, *Gp, *A;
    cudaGetSymbolAddress((void**)&rhs, d_rhs);
    cudaGetSymbolAddress((void**)&lfp, d_lfp);
    cudaGetSymbolAddress((void**)&Gp,  d_Gp);
    cudaGetSymbolAddress((void**)&A,   d_A);

    static cudaStream_t sB = nullptr;
    static cudaEvent_t e1a, e1b, eSa, eSb;
    if (!sB) {
        cudaStreamCreateWithFlags(&sB, cudaStreamNonBlocking);
        cudaEventCreateWithFlags(&e1a, cudaEventDisableTiming);
        cudaEventCreateWithFlags(&e1b, cudaEventDisableTiming);
        cudaEventCreateWithFlags(&eSa, cudaEventDisableTiming);
        cudaEventCreateWithFlags(&eSb, cudaEventDisableTiming);
    }

    // half A = batches 0-7 (bt 0-191), half B = batches 8-15 (bt 192-383)
    k1_pass<<<HBT*8, 128>>>(x, U1, U3, rhs, lfp, 0);
    cudaEventRecord(e1a, 0);

    // scores for half A on side stream (overlaps k1 half B)
    cudaStreamWaitEvent(sB, e1a, 0);
    k2_gemm<<<dim3(HBT/32, KSPLIT), 128, 0, sB>>>(rhs, U2, Gp, 0);
    k3_scores<<<HB, 576, 0, sB>>>(lfp, Gp, be, Ve, A, 0);
    cudaEventRecord(eSa, sB);

    k1_pass<<<HBT*8, 128>>>(x, U1, U3, rhs, lfp, HBT);
    cudaEventRecord(e1b, 0);

    // scores for half B on side stream (overlaps start of k4 half B wait window)
    cudaStreamWaitEvent(sB, e1b, 0);
    k2_gemm<<<dim3(HBT/32, KSPLIT), 128, 0, sB>>>(rhs, U2, Gp, HBT);
    k3_scores<<<HB, 576, 0, sB>>>(lfp, Gp, be, Ve, A, HB);
    cudaEventRecord(eSb, sB);

    // k4 half B first (x[8..15] hot in L2 from k1b), then half A
    cudaStreamWaitEvent(0, eSb, 0);
    k4_out<<<dim3(NF4/128, HB), 128>>>((const float4*)x, A, (float4*)d_out, HB);
    cudaStreamWaitEvent(0, eSa, 0);
    k4_out<<<dim3(NF4/128, HB), 128>>>((const float4*)x, A, (float4*)d_out, 0);
}

// round 10
// speedup vs baseline: 1.4045x; 1.1381x over previous
#include <cuda_runtime.h>
#include <cuda_bf16.h>

// Problem constants
#define BB 16
#define TT 24
#define NN 2048
#define FF 64
#define BT (BB*TT)          // 384
#define NF (NN*FF)          // 131072
#define NF4 (NF/4)          // 32768 float4 per (b,t) row
#define KSPLIT 16

// Scratch (device globals; no allocation allowed). All fully overwritten each call.
__device__ float d_rhs[BT*NN];         // 3 MB
__device__ float d_lfp[8*BT*FF];       // lhs_f partials (8 octants per bt)
__device__ float d_Gp [KSPLIT*BT*FF];  // K-split partials of G
__device__ float d_A  [BB*TT*TT];      // attention weights

// ---------------------------------------------------------------------------
// Kernel 1: single pass over ALL of x. Each CTA (128 thr) handles one OCTANT
// (256 rows) of the n-range of one (b,t). grid = BT*8 = 3072 CTAs
// (20.8 CTAs/SM) for deep DRAM latency hiding.
//   rhs[n]        = sum_f x[n,f]*U3[f]
//   lfp[bt*8+oct] = partial over this octant of sum_n x[n,f]*U1[n]
// ---------------------------------------------------------------------------
__global__ __launch_bounds__(128) void k1_pass(
    const float* __restrict__ x, const float* __restrict__ U1,
    const float* __restrict__ U3, float* __restrict__ rhs,
    float* __restrict__ lfp)
{
    const int bt   = blockIdx.x >> 3;
    const int oct  = blockIdx.x & 7;
    const int w    = threadIdx.x >> 5;
    const int lane = threadIdx.x & 31;
    const int r    = lane >> 2;
    const int q    = lane & 3;
    const float4* xb = (const float4*)(x + (size_t)bt * NF);

    float4 u3[4];
    #pragma unroll
    for (int j = 0; j < 4; j++) u3[j] = ((const float4*)U3)[q + 4*j];

    float4 acc[4];
    #pragma unroll
    for (int j = 0; j < 4; j++) acc[j] = make_float4(0.f,0.f,0.f,0.f);

    const int n0 = oct * 256 + w * 64;
    #pragma unroll 4
    for (int k = 0; k < 8; k++) {
        const int n = n0 + 8*k + r;
        const float4* row = xb + (size_t)n * 16;
        const float u1 = __ldg(U1 + n);
        float d = 0.f;
        #pragma unroll
        for (int j = 0; j < 4; j++) {
            float4 v = row[q + 4*j];
            d += v.x*u3[j].x + v.y*u3[j].y + v.z*u3[j].z + v.w*u3[j].w;
            acc[j].x += v.x*u1; acc[j].y += v.y*u1;
            acc[j].z += v.z*u1; acc[j].w += v.w*u1;
        }
        d += __shfl_down_sync(0xffffffffu, d, 2, 4);
        d += __shfl_down_sync(0xffffffffu, d, 1, 4);
        if (q == 0) rhs[bt*NN + n] = d;
    }

    #pragma unroll
    for (int off = 16; off >= 4; off >>= 1) {
        #pragma unroll
        for (int j = 0; j < 4; j++) {
            acc[j].x += __shfl_down_sync(0xffffffffu, acc[j].x, off);
            acc[j].y += __shfl_down_sync(0xffffffffu, acc[j].y, off);
            acc[j].z += __shfl_down_sync(0xffffffffu, acc[j].z, off);
            acc[j].w += __shfl_down_sync(0xffffffffu, acc[j].w, off);
        }
    }

    __shared__ float sred[4][FF];
    if (lane < 4) {
        #pragma unroll
        for (int j = 0; j < 4; j++)
            ((float4*)sred[w])[q + 4*j] = acc[j];
    }
    __syncthreads();
    if (threadIdx.x < FF) {
        float t = 0.f;
        #pragma unroll
        for (int p = 0; p < 4; p++) t += sred[p][threadIdx.x];
        lfp[(bt*8 + oct)*FF + threadIdx.x] = t;
    }
}

// ---------------------------------------------------------------------------
// Kernel 2: G = rhs(384 x 2048) @ U2(2048 x 64), K-split into 16 partials.
// Thread = 4 rows x 4 cols. grid = (12, 16) = 192 CTAs.
// ---------------------------------------------------------------------------
__global__ __launch_bounds__(128) void k2_gemm(
    const float* __restrict__ rhs, const float* __restrict__ U2,
    float* __restrict__ Gp)
{
    __shared__ float4 Us4[64*16];
    __shared__ float  Rs [32*68];
    const int m0 = blockIdx.x * 32;
    const int k0 = blockIdx.y * 128;
    const int c4 = threadIdx.x & 15;
    const int rg = threadIdx.x >> 4;

    float4 acc[4];
    #pragma unroll
    for (int r = 0; r < 4; r++) acc[r] = make_float4(0.f,0.f,0.f,0.f);

    for (int kc = 0; kc < 128; kc += 64) {
        const int kb = k0 + kc;
        __syncthreads();
        #pragma unroll
        for (int i = 0; i < 8; i++) {
            int e = threadIdx.x + i*128;
            int kk = e >> 4, cc = e & 15;
            Us4[e] = ((const float4*)(U2 + (size_t)(kb + kk)*FF))[cc];
        }
        #pragma unroll
        for (int i = 0; i < 4; i++) {
            int e = threadIdx.x + i*128;
            int row = e >> 4, kq = e & 15;
            float4 v = *(const float4*)(rhs + (size_t)(m0 + row)*NN + kb + kq*4);
            *(float4*)&Rs[row*68 + kq*4] = v;
        }
        __syncthreads();
        #pragma unroll
        for (int kk = 0; kk < 64; kk++) {
            const float4 u = Us4[kk*16 + c4];
            #pragma unroll
            for (int r = 0; r < 4; r++) {
                const float rv = Rs[(rg*4 + r)*68 + kk];
                acc[r].x += rv*u.x; acc[r].y += rv*u.y;
                acc[r].z += rv*u.z; acc[r].w += rv*u.w;
            }
        }
    }
    float* g = Gp + (size_t)blockIdx.y * (BT*FF);
    #pragma unroll
    for (int r = 0; r < 4; r++)
        *(float4*)&g[(m0 + rg*4 + r)*FF + c4*4] = acc[r];
}

// ---------------------------------------------------------------------------
// Kernel 3: per batch: product -> sigmoid(+be) -> E -> softmax (8 lfp partials).
// ---------------------------------------------------------------------------
__global__ __launch_bounds__(576) void k3_scores(
    const float* __restrict__ lfp, const float* __restrict__ Gp,
    const float* __restrict__ be, const float* __restrict__ Ve,
    float* __restrict__ A)
{
    const int b = blockIdx.x;
    __shared__ float lfs[TT*65], Gs[TT*65], sg[TT*25], Em[TT*25];
    __shared__ float cmax[TT], csum[TT];
    const int tid = threadIdx.x;

    for (int e = tid; e < TT*FF; e += 576) {
        int t = e >> 6, f = e & 63;
        const int bt = b*TT + t;
        float lv = 0.f;
        #pragma unroll
        for (int p = 0; p < 8; p++) lv += lfp[(bt*8 + p)*FF + f];
        lfs[t*65 + f] = lv;
        float g = 0.f;
        #pragma unroll
        for (int ks = 0; ks < KSPLIT; ks++)
            g += Gp[(size_t)ks*(BT*FF) + bt*FF + f];
        Gs[t*65 + f] = g;
    }
    __syncthreads();

    const int t = tid / TT;
    const int s = tid % TT;
    float p = 0.f;
    #pragma unroll
    for (int f = 0; f < FF; f++)
        p += lfs[t*65 + f] * Gs[s*65 + f];
    sg[t*25 + s] = 1.f / (1.f + __expf(-(p + be[t*TT + s])));
    __syncthreads();

    float e = 0.f;
    #pragma unroll
    for (int s2 = 0; s2 < TT; s2++)
        e += Ve[t*TT + s2] * sg[s2*25 + s];
    Em[t*25 + s] = e;
    __syncthreads();

    if (t == 0) {
        float m = -1e30f;
        #pragma unroll
        for (int tt2 = 0; tt2 < TT; tt2++) m = fmaxf(m, Em[tt2*25 + s]);
        cmax[s] = m;
    }
    __syncthreads();
    const float ex = __expf(Em[t*25 + s] - cmax[s]);
    Em[t*25 + s] = ex;
    __syncthreads();
    if (t == 0) {
        float sm = 0.f;
        #pragma unroll
        for (int tt2 = 0; tt2 < TT; tt2++) sm += Em[tt2*25 + s];
        csum[s] = sm;
    }
    __syncthreads();
    A[b*TT*TT + t*TT + s] = ex / csum[s];
}

// ---------------------------------------------------------------------------
// Kernel 4: out[b,s,nf] = sum_t x[b,t,nf] * A[b,t,s].
// float4 column per thread (xr = 24 x float4), s in pairs, A as float2 in smem,
// 4 CTAs/SM. Reverse batch order for L2 reuse of k1's tail.
// ---------------------------------------------------------------------------
__global__ __launch_bounds__(128, 4) void k4_out(
    const float4* __restrict__ x4, const float* __restrict__ A,
    float4* __restrict__ out4)
{
    __shared__ float2 As2[TT*12];
    const int b = (BB - 1) - blockIdx.y;
    const float2* Ab2 = (const float2*)(A + b*TT*TT);
    for (int i = threadIdx.x; i < TT*12; i += 128)
        As2[i] = Ab2[i];
    __syncthreads();

    const size_t c = (size_t)blockIdx.x * 128 + threadIdx.x;
    const float4* xb = x4 + (size_t)b * TT * NF4 + c;

    float4 xr[TT];
    #pragma unroll
    for (int t = 0; t < TT; t++) xr[t] = xb[(size_t)t * NF4];

    float4* ob = out4 + (size_t)b * TT * NF4 + c;
    #pragma unroll 1
    for (int sp = 0; sp < 12; sp++) {
        float4 a0 = make_float4(0.f,0.f,0.f,0.f);
        float4 a1 = make_float4(0.f,0.f,0.f,0.f);
        #pragma unroll
        for (int t = 0; t < TT; t++) {
            const float2 av = As2[t*12 + sp];
            a0.x += xr[t].x*av.x; a0.y += xr[t].y*av.x; a0.z += xr[t].z*av.x; a0.w += xr[t].w*av.x;
            a1.x += xr[t].x*av.y; a1.y += xr[t].y*av.y; a1.z += xr[t].z*av.y; a1.w += xr[t].w*av.y;
        }
        ob[(size_t)(2*sp    ) * NF4] = a0;
        ob[(size_t)(2*sp + 1) * NF4] = a1;
    }
}

// ---------------------------------------------------------------------------
extern "C" void kernel_launch(void* const* d_in, const int* in_sizes, int n_in,
                              void* d_out, int out_size)
{
    const float* x  = (const float*)d_in[0];
    const float* U1 = (const float*)d_in[1];
    const float* U2 = (const float*)d_in[2];
    const float* U3 = (const float*)d_in[3];
    const float* be = (const float*)d_in[4];
    const float* Ve = (const float*)d_in[5];

    float *rhs, *lfp, *Gp, *A;
    cudaGetSymbolAddress((void**)&rhs, d_rhs);
    cudaGetSymbolAddress((void**)&lfp, d_lfp);
    cudaGetSymbolAddress((void**)&Gp,  d_Gp);
    cudaGetSymbolAddress((void**)&A,   d_A);

    k1_pass<<<BT*8, 128>>>(x, U1, U3, rhs, lfp);
    k2_gemm<<<dim3(BT/32, KSPLIT), 128>>>(rhs, U2, Gp);
    k3_scores<<<BB, 576>>>(lfp, Gp, be, Ve, A);
    k4_out<<<dim3(NF4/128, BB), 128>>>((const float4*)x, A, (float4*)d_out);
}